// round 2
// baseline (speedup 1.0000x reference)
#include <cuda_runtime.h>
#include <math.h>

// LSTM_2370821948014 — fused LSTM cell, round 1 (SIMT fp32, logits coverage fix)
//
// B=65536, I=128, H=256, O=256.  K = I+H = 384.
// gates  = combined @ w_i2h^T + b_i2h   [B,1024], gate order (h, ig, fg, og)
// new_h  = sig(og) * tanh(sig(fg)*hidden + sig(ig)*tanh(h))
// logits = combined @ w_i2o^T + b_i2o   [B,256] -> log_softmax
// out layout: [ log_softmax (B*256) | new_hidden (B*256) ]  (float32)

static constexpr int BATCH   = 65536;
static constexpr int IDIM    = 128;
static constexpr int HDIM    = 256;
static constexpr int ODIM    = 256;
static constexpr int KDIM    = 384;     // IDIM + HDIM
static constexpr int RM      = 64;      // rows per CTA
static constexpr int KC      = 96;      // K chunk
static constexpr int NKC     = KDIM / KC;  // 4
static constexpr int THREADS = 256;

// SMEM plan (floats):
//   As : RM x 384                    = 24576
//   Ws : 128 x 97 (pitch 97, odd => conflict-free stride-1 v reads) = 12416
//   Ls : RM x 257 (logits)           = 16448
//   Red: RM x 4                      = 256
static constexpr int AS_OFF  = 0;
static constexpr int AS_PITCH = 384;
static constexpr int WS_OFF  = AS_OFF + RM * AS_PITCH;     // 24576
static constexpr int WS_PITCH = 97;
static constexpr int LS_OFF  = WS_OFF + 128 * WS_PITCH;    // 36992
static constexpr int LS_PITCH = 257;
static constexpr int RED_OFF = LS_OFF + RM * LS_PITCH;     // 53440
static constexpr int SMEM_FLOATS = RED_OFF + RM * 4;       // 53696
static constexpr int SMEM_BYTES  = SMEM_FLOATS * 4;        // 214784 < 227KB

__device__ __forceinline__ float sigmoidf_fast(float x) {
    return 1.0f / (1.0f + __expf(-x));
}

__global__ __launch_bounds__(THREADS, 1)
void lstm_fused_kernel(const float* __restrict__ input,
                       const float* __restrict__ hidden,
                       const float* __restrict__ w_i2h,
                       const float* __restrict__ b_i2h,
                       const float* __restrict__ w_i2o,
                       const float* __restrict__ b_i2o,
                       float* __restrict__ out)
{
    extern __shared__ float smem[];
    float* As  = smem + AS_OFF;
    float* Ws  = smem + WS_OFF;
    float* Ls  = smem + LS_OFF;
    float* Red = smem + RED_OFF;

    const int tid = threadIdx.x;
    const int tx  = tid & 15;          // 0..15 : column group
    const int ty  = tid >> 4;          // 0..15 : row group (4 rows each)
    const int rbase = blockIdx.x * RM;

    // ---- Stage A = [input | hidden] for this row block (float4 loads) ----
    for (int idx = tid; idx < RM * (IDIM / 4); idx += THREADS) {
        int r = idx >> 5;              // IDIM/4 = 32
        int c = (idx & 31) << 2;
        float4 v = *reinterpret_cast<const float4*>(
            input + (size_t)(rbase + r) * IDIM + c);
        *reinterpret_cast<float4*>(&As[r * AS_PITCH + c]) = v;
    }
    for (int idx = tid; idx < RM * (HDIM / 4); idx += THREADS) {
        int r = idx >> 6;              // HDIM/4 = 64
        int c = (idx & 63) << 2;
        float4 v = *reinterpret_cast<const float4*>(
            hidden + (size_t)(rbase + r) * HDIM + c);
        *reinterpret_cast<float4*>(&As[r * AS_PITCH + IDIM + c]) = v;
    }
    __syncthreads();

    const int r0 = ty * 4;             // local row base for this thread

    // ================= Part 1: gates GEMM + LSTM epilogue =================
    // j-chunk of 32; each thread owns (4 rows) x (2 j) x (4 gates).
    for (int jc = 0; jc < HDIM / 32; ++jc) {
        float acc[4][2][4];
        #pragma unroll
        for (int a = 0; a < 4; ++a)
            #pragma unroll
            for (int b = 0; b < 2; ++b)
                #pragma unroll
                for (int g = 0; g < 4; ++g)
                    acc[a][b][g] = 0.0f;

        for (int kc = 0; kc < NKC; ++kc) {
            __syncthreads();           // protect Ws from previous use
            // Stage W tile: v = g*32 + jl -> w_i2h row g*256 + jc*32 + jl
            for (int idx = tid; idx < 128 * KC; idx += THREADS) {
                int v = idx / KC;
                int k = idx - v * KC;
                int g  = v >> 5;
                int jl = v & 31;
                int grow = g * HDIM + jc * 32 + jl;
                Ws[v * WS_PITCH + k] =
                    w_i2h[(size_t)grow * KDIM + kc * KC + k];
            }
            __syncthreads();

            const float* A0 = &As[(r0 + 0) * AS_PITCH + kc * KC];
            const float* A1 = A0 + AS_PITCH;
            const float* A2 = A1 + AS_PITCH;
            const float* A3 = A2 + AS_PITCH;

            #pragma unroll 4
            for (int k = 0; k < KC; ++k) {
                float a0 = A0[k], a1 = A1[k], a2 = A2[k], a3 = A3[k];
                #pragma unroll
                for (int jh = 0; jh < 2; ++jh) {
                    int jl = tx + jh * 16;
                    #pragma unroll
                    for (int g = 0; g < 4; ++g) {
                        float w = Ws[(g * 32 + jl) * WS_PITCH + k];
                        acc[0][jh][g] = fmaf(a0, w, acc[0][jh][g]);
                        acc[1][jh][g] = fmaf(a1, w, acc[1][jh][g]);
                        acc[2][jh][g] = fmaf(a2, w, acc[2][jh][g]);
                        acc[3][jh][g] = fmaf(a3, w, acc[3][jh][g]);
                    }
                }
            }
        }

        // Epilogue: all 4 gates of (row, j) live in this thread.
        float* outNH = out + (size_t)BATCH * ODIM;
        #pragma unroll
        for (int jh = 0; jh < 2; ++jh) {
            int j = jc * 32 + tx + jh * 16;
            float bh = b_i2h[j];
            float bi = b_i2h[HDIM + j];
            float bf = b_i2h[2 * HDIM + j];
            float bo = b_i2h[3 * HDIM + j];
            #pragma unroll
            for (int rr = 0; rr < 4; ++rr) {
                float hg = tanhf(acc[rr][jh][0] + bh);
                float ig = sigmoidf_fast(acc[rr][jh][1] + bi);
                float fg = sigmoidf_fast(acc[rr][jh][2] + bf);
                float og = sigmoidf_fast(acc[rr][jh][3] + bo);
                float hv = As[(r0 + rr) * AS_PITCH + IDIM + j];
                float nh = og * tanhf(fg * hv + ig * hg);
                outNH[(size_t)(rbase + r0 + rr) * HDIM + j] = nh;
            }
        }
    }

    // ================= Part 2: logits GEMM -> SMEM =================
    // Each nc stages 128 weight rows; each thread now owns 4 rows x 8 cols
    // (c = nc*128 + tx + jh*16, jh in 0..7) so all 128 columns are covered.
    for (int nc = 0; nc < 2; ++nc) {
        float acc[4][8];
        #pragma unroll
        for (int a = 0; a < 4; ++a)
            #pragma unroll
            for (int b = 0; b < 8; ++b)
                acc[a][b] = 0.0f;

        for (int kc = 0; kc < NKC; ++kc) {
            __syncthreads();
            for (int idx = tid; idx < 128 * KC; idx += THREADS) {
                int v = idx / KC;
                int k = idx - v * KC;
                int grow = nc * 128 + v;
                Ws[v * WS_PITCH + k] =
                    w_i2o[(size_t)grow * KDIM + kc * KC + k];
            }
            __syncthreads();

            const float* A0 = &As[(r0 + 0) * AS_PITCH + kc * KC];
            const float* A1 = A0 + AS_PITCH;
            const float* A2 = A1 + AS_PITCH;
            const float* A3 = A2 + AS_PITCH;

            #pragma unroll 2
            for (int k = 0; k < KC; ++k) {
                float a0 = A0[k], a1 = A1[k], a2 = A2[k], a3 = A3[k];
                #pragma unroll
                for (int jh = 0; jh < 8; ++jh) {
                    float w = Ws[(tx + jh * 16) * WS_PITCH + k];
                    acc[0][jh] = fmaf(a0, w, acc[0][jh]);
                    acc[1][jh] = fmaf(a1, w, acc[1][jh]);
                    acc[2][jh] = fmaf(a2, w, acc[2][jh]);
                    acc[3][jh] = fmaf(a3, w, acc[3][jh]);
                }
            }
        }

        #pragma unroll
        for (int jh = 0; jh < 8; ++jh) {
            int c = nc * 128 + tx + jh * 16;
            float bias = b_i2o[c];
            #pragma unroll
            for (int rr = 0; rr < 4; ++rr)
                Ls[(r0 + rr) * LS_PITCH + c] = acc[rr][jh] + bias;
        }
    }
    __syncthreads();

    // ================= Part 3: log_softmax over 256 cols =================
    // 4 threads per row; thread q owns float4 chunks c4 = q + 4*i (i<16)
    {
        const int r = tid >> 2;
        const int q = tid & 3;
        const float* row = &Ls[r * LS_PITCH];

        float m = -3.4e38f;
        #pragma unroll 4
        for (int i = 0; i < 16; ++i) {
            int c = (q + 4 * i) * 4;
            m = fmaxf(m, fmaxf(fmaxf(row[c], row[c + 1]),
                               fmaxf(row[c + 2], row[c + 3])));
        }
        Red[r * 4 + q] = m;
        __syncthreads();
        float M = fmaxf(fmaxf(Red[r * 4 + 0], Red[r * 4 + 1]),
                        fmaxf(Red[r * 4 + 2], Red[r * 4 + 3]));
        __syncthreads();   // before reusing Red

        float s = 0.0f;
        #pragma unroll 4
        for (int i = 0; i < 16; ++i) {
            int c = (q + 4 * i) * 4;
            s += __expf(row[c]     - M);
            s += __expf(row[c + 1] - M);
            s += __expf(row[c + 2] - M);
            s += __expf(row[c + 3] - M);
        }
        Red[r * 4 + q] = s;
        __syncthreads();
        float S = Red[r * 4 + 0] + Red[r * 4 + 1] +
                  Red[r * 4 + 2] + Red[r * 4 + 3];
        float lse = M + logf(S);

        float* orow = out + (size_t)(rbase + r) * ODIM;
        #pragma unroll 4
        for (int i = 0; i < 16; ++i) {
            int c = (q + 4 * i) * 4;
            float4 o;
            o.x = row[c]     - lse;
            o.y = row[c + 1] - lse;
            o.z = row[c + 2] - lse;
            o.w = row[c + 3] - lse;
            *reinterpret_cast<float4*>(orow + c) = o;
        }
    }
}

extern "C" void kernel_launch(void* const* d_in, const int* in_sizes, int n_in,
                              void* d_out, int out_size)
{
    (void)in_sizes; (void)n_in; (void)out_size;
    const float* input  = (const float*)d_in[0];
    const float* hidden = (const float*)d_in[1];
    const float* w_i2h  = (const float*)d_in[2];
    const float* b_i2h  = (const float*)d_in[3];
    const float* w_i2o  = (const float*)d_in[4];
    const float* b_i2o  = (const float*)d_in[5];
    float* out = (float*)d_out;

    cudaFuncSetAttribute(lstm_fused_kernel,
                         cudaFuncAttributeMaxDynamicSharedMemorySize,
                         SMEM_BYTES);
    lstm_fused_kernel<<<BATCH / RM, THREADS, SMEM_BYTES>>>(
        input, hidden, w_i2h, b_i2h, w_i2o, b_i2o, out);
}

// round 4
// speedup vs baseline: 5.3729x; 5.3729x over previous
#include <cuda_runtime.h>
#include <cstdint>
#include <math.h>

// LSTM_2370821948014 — round 3: legacy mma.sync tf32 (tcgen05 unavailable:
// harness PTX targets sm_103 base, which rejects all tcgen05/TMEM ops).
//
// B=65536, I=128, H=256, O=256, K=384.
// Kernel 1 (repack): weights -> 60 contiguous 32KB tiles in __device__ scratch,
//   gate-interleaved column packing + XOR bank swizzle + cvt.rna.tf32.
// Kernel 2 (main): 1024 CTAs x 64 rows. A staged once (tf32) in SMEM; W tiles
//   double-buffered via cp.async.bulk + mbarrier; 8 warps (2M x 4N), warp tile
//   32x64 via mma.sync.m16n8k8.tf32. Gates epilogue fully in-register; logits
//   log_softmax via shfl + small SMEM cross-warp reduction.

static constexpr int BATCH = 65536;
static constexpr int ODIM  = 256;
static constexpr int KDIM  = 384;
static constexpr int MT    = 64;          // rows per CTA
static constexpr int THREADS = 256;
static constexpr int NTILES  = 60;        // 5 chunks x 12 k-tiles
static constexpr int TILE_U32 = 8192;     // 256 rows x 32 k  (32KB)

// SMEM byte offsets
static constexpr int PA      = 388;                   // A pitch (floats)
static constexpr int SM_A    = 0;                     // 64*388*4 = 99328
static constexpr int SM_W    = 99328;                 // 2 x 32768
static constexpr int WB      = 32768;
static constexpr int SM_BIAS = 164864;                // 1280 floats
static constexpr int SM_REDM = 169984;                // 64*4 floats
static constexpr int SM_REDS = 171008;                // 64*4 floats
static constexpr int SM_MB   = 172032;                // 2 x 8B mbarrier
static constexpr int SMEM_TOTAL = 172064;

__device__ uint32_t w_packed[NTILES * TILE_U32];      // 1.97MB static scratch

// ---------------- helpers ----------------

__device__ __forceinline__ uint32_t smem_u32(const void* p) {
    uint32_t a;
    asm("{ .reg .u64 t; cvta.to.shared.u64 t, %1; cvt.u32.u64 %0, t; }"
        : "=r"(a) : "l"(p));
    return a;
}

__device__ __forceinline__ uint32_t f2tf(float x) {
    uint32_t u;
    asm("cvt.rna.tf32.f32 %0, %1;" : "=r"(u) : "f"(x));
    return u;
}

__device__ __forceinline__ void mbar_init(uint32_t a) {
    asm volatile("mbarrier.init.shared.b64 [%0], %1;" :: "r"(a), "r"(1u) : "memory");
}

__device__ __forceinline__ void mbar_expect_tx(uint32_t a, uint32_t bytes) {
    asm volatile("mbarrier.arrive.expect_tx.shared.b64 _, [%0], %1;"
                 :: "r"(a), "r"(bytes) : "memory");
}

__device__ __forceinline__ void mbar_wait(uint32_t a, uint32_t parity) {
    asm volatile(
        "{\n\t"
        ".reg .pred P;\n\t"
        "W%=:\n\t"
        "mbarrier.try_wait.parity.acquire.cta.shared::cta.b64 P, [%0], %1, 0x989680;\n\t"
        "@P bra D%=;\n\t"
        "bra W%=;\n\t"
        "D%=:\n\t"
        "}"
        :: "r"(a), "r"(parity) : "memory");
}

__device__ __forceinline__ void bulk_ld(uint32_t dst, const void* src,
                                        uint32_t bytes, uint32_t mbar) {
    asm volatile(
        "cp.async.bulk.shared::cluster.global.mbarrier::complete_tx::bytes "
        "[%0], [%1], %2, [%3];"
        :: "r"(dst), "l"(src), "r"(bytes), "r"(mbar) : "memory");
}

__device__ __forceinline__ void mma8(float* d, const uint32_t* a,
                                     uint32_t b0, uint32_t b1) {
    asm volatile(
        "mma.sync.aligned.m16n8k8.row.col.f32.tf32.tf32.f32 "
        "{%0,%1,%2,%3}, {%4,%5,%6,%7}, {%8,%9}, {%0,%1,%2,%3};"
        : "+f"(d[0]), "+f"(d[1]), "+f"(d[2]), "+f"(d[3])
        : "r"(a[0]), "r"(a[1]), "r"(a[2]), "r"(a[3]), "r"(b0), "r"(b1));
}

__device__ __forceinline__ float sigf(float x) {
    return 1.0f / (1.0f + __expf(-x));
}
__device__ __forceinline__ float tanh_fast(float x) {
    x = fminf(fmaxf(x, -15.0f), 15.0f);
    float e = __expf(2.0f * x);
    return (e - 1.0f) / (e + 1.0f);
}

// ---------------- repack kernel ----------------
// tile t = chunk*12 + kk.  Gates chunks (0..3): tile row v -> w_i2h row
//   g*256 + chunk*64 + wn*16 + jl8*8 + jlo  with v = wn*64 + jl8*32 + g*8 + jlo.
// Logits chunk (4): row v -> w_i2o row v.
// Element (v, kw) stored at v*32 + (kw ^ ((v&7)*4))  (XOR bank swizzle).

__global__ void repack_kernel(const float* __restrict__ w_i2h,
                              const float* __restrict__ w_i2o)
{
    int i = blockIdx.x * 256 + threadIdx.x;
    if (i >= NTILES * TILE_U32) return;
    int t  = i >> 13;
    int e  = i & 8191;
    int v  = e >> 5;
    int kw = e & 31;
    int chunk = t / 12;
    int kk    = t - chunk * 12;
    const float* src;
    int row;
    if (chunk < 4) {
        int wn  = v >> 6;
        int lc  = v & 63;
        int jl8 = lc >> 5;
        int g   = (lc >> 3) & 3;
        int jlo = lc & 7;
        row = g * 256 + chunk * 64 + wn * 16 + jl8 * 8 + jlo;
        src = w_i2h;
    } else {
        row = v;
        src = w_i2o;
    }
    float x = src[(size_t)row * KDIM + kk * 32 + kw];
    w_packed[t * TILE_U32 + v * 32 + (kw ^ ((v & 7) * 4))] = f2tf(x);
}

// ---------------- main kernel ----------------

__global__ __launch_bounds__(THREADS, 1)
void lstm_mma_kernel(const float* __restrict__ input,
                     const float* __restrict__ hidden,
                     const float* __restrict__ b_i2h,
                     const float* __restrict__ b_i2o,
                     float* __restrict__ out)
{
    extern __shared__ char smem[];
    const uint32_t sbase = smem_u32(smem);
    const int tid  = threadIdx.x;
    const int wid  = tid >> 5;
    const int lane = tid & 31;
    const int wm   = wid >> 2;          // 0..1 (M)
    const int wn   = wid & 3;           // 0..3 (N)
    const int gID  = lane >> 2;         // 0..7
    const int lq   = lane & 3;          // 0..3
    const int sw   = gID << 2;          // bank swizzle term
    const int rbase = blockIdx.x * MT;

    uint32_t* Au = (uint32_t*)(smem + SM_A);
    float*    Af = (float*)(smem + SM_A);
    float*    bias = (float*)(smem + SM_BIAS);
    const uint32_t mb0 = sbase + SM_MB;
    const uint32_t mb1 = sbase + SM_MB + 8;

    if (tid == 0) { mbar_init(mb0); mbar_init(mb1); }
    __syncthreads();

    // issue tile 0 immediately (overlaps with A/bias staging)
    if (tid == 0) {
        mbar_expect_tx(mb0, WB);
        bulk_ld(sbase + SM_W, w_packed, WB, mb0);
    }

    // stage A = [input | hidden], tf32-converted, pitch 388
    for (int idx = tid; idx < MT * 96; idx += THREADS) {
        int r  = idx / 96;
        int c4 = idx - r * 96;
        float4 v = (c4 < 32)
            ? *(const float4*)(input  + (size_t)(rbase + r) * 128 + c4 * 4)
            : *(const float4*)(hidden + (size_t)(rbase + r) * 256 + (c4 - 32) * 4);
        uint4 u;
        u.x = f2tf(v.x); u.y = f2tf(v.y); u.z = f2tf(v.z); u.w = f2tf(v.w);
        *(uint4*)(Au + r * PA + c4 * 4) = u;
    }
    for (int i = tid; i < 1280; i += THREADS)
        bias[i] = (i < 1024) ? b_i2h[i] : b_i2o[i - 1024];
    __syncthreads();

    float* outLS = out;
    float* outNH = out + (size_t)BATCH * ODIM;

    float acc[2][8][4];
    #pragma unroll
    for (int m = 0; m < 2; ++m)
        #pragma unroll
        for (int n = 0; n < 8; ++n)
            #pragma unroll
            for (int c = 0; c < 4; ++c) acc[m][n][c] = 0.0f;

    int ub0 = 0, ub1 = 0;
    const int ra0 = (wm * 32 + gID) * PA;       // A row base (mt=0)
    const int ra1 = (wm * 32 + 16 + gID) * PA;  // mt=1

    for (int t = 0; t < NTILES; ++t) {
        const int buf = t & 1;
        if (t + 1 < NTILES && tid == 0) {
            uint32_t mbn = (buf ? mb0 : mb1);
            mbar_expect_tx(mbn, WB);
            bulk_ld(sbase + SM_W + (buf ^ 1) * WB,
                    w_packed + (size_t)(t + 1) * TILE_U32, WB, mbn);
        }
        if (buf == 0) { mbar_wait(mb0, ub0 & 1); ub0++; }
        else          { mbar_wait(mb1, ub1 & 1); ub1++; }

        // ---- compute: 4 k-steps of 8 on this 32-k tile ----
        const uint32_t* Wu = (const uint32_t*)(smem + SM_W + buf * WB);
        const int kt = (t % 12) * 32;
        #pragma unroll
        for (int ks = 0; ks < 4; ++ks) {
            const int k0 = kt + ks * 8;
            uint32_t a[2][4];
            a[0][0] = Au[ra0 + k0 + lq];
            a[0][1] = Au[ra0 + 8 * PA + k0 + lq];
            a[0][2] = Au[ra0 + k0 + lq + 4];
            a[0][3] = Au[ra0 + 8 * PA + k0 + lq + 4];
            a[1][0] = Au[ra1 + k0 + lq];
            a[1][1] = Au[ra1 + 8 * PA + k0 + lq];
            a[1][2] = Au[ra1 + k0 + lq + 4];
            a[1][3] = Au[ra1 + 8 * PA + k0 + lq + 4];
            const int kk0 = ks * 8;
            #pragma unroll
            for (int nt = 0; nt < 8; ++nt) {
                const int vr = (wn * 64 + nt * 8 + gID) * 32;
                uint32_t b0 = Wu[vr + ((kk0 + lq) ^ sw)];
                uint32_t b1 = Wu[vr + ((kk0 + lq + 4) ^ sw)];
                mma8(acc[0][nt], a[0], b0, b1);
                mma8(acc[1][nt], a[1], b0, b1);
            }
        }

        if ((t % 12) == 11) {
            const int chunk = t / 12;
            if (chunk < 4) {
                // ---- LSTM epilogue: all 4 gates in-register ----
                #pragma unroll
                for (int mt = 0; mt < 2; ++mt)
                    #pragma unroll
                    for (int rh = 0; rh < 2; ++rh)
                        #pragma unroll
                        for (int jl8 = 0; jl8 < 2; ++jl8) {
                            int r  = wm * 32 + mt * 16 + rh * 8 + gID;
                            int j0 = chunk * 64 + wn * 16 + jl8 * 8 + lq * 2;
                            int ci = rh * 2;
                            float h0 = acc[mt][jl8*4+0][ci]   + bias[j0];
                            float h1 = acc[mt][jl8*4+0][ci+1] + bias[j0+1];
                            float i0 = acc[mt][jl8*4+1][ci]   + bias[256+j0];
                            float i1 = acc[mt][jl8*4+1][ci+1] + bias[256+j0+1];
                            float f0 = acc[mt][jl8*4+2][ci]   + bias[512+j0];
                            float f1 = acc[mt][jl8*4+2][ci+1] + bias[512+j0+1];
                            float o0 = acc[mt][jl8*4+3][ci]   + bias[768+j0];
                            float o1 = acc[mt][jl8*4+3][ci+1] + bias[768+j0+1];
                            float hv0 = Af[r * PA + 128 + j0];
                            float hv1 = Af[r * PA + 128 + j0 + 1];
                            float2 nh;
                            nh.x = sigf(o0) * tanh_fast(sigf(f0) * hv0 + sigf(i0) * tanh_fast(h0));
                            nh.y = sigf(o1) * tanh_fast(sigf(f1) * hv1 + sigf(i1) * tanh_fast(h1));
                            *(float2*)(outNH + (size_t)(rbase + r) * 256 + j0) = nh;
                        }
                #pragma unroll
                for (int m = 0; m < 2; ++m)
                    #pragma unroll
                    for (int n = 0; n < 8; ++n)
                        #pragma unroll
                        for (int c = 0; c < 4; ++c) acc[m][n][c] = 0.0f;
            } else {
                // ---- logits epilogue: log_softmax ----
                float* redm = (float*)(smem + SM_REDM);
                float* reds = (float*)(smem + SM_REDS);

                // add bias in place
                #pragma unroll
                for (int mt = 0; mt < 2; ++mt)
                    #pragma unroll
                    for (int nt = 0; nt < 8; ++nt) {
                        int n0 = wn * 64 + nt * 8 + lq * 2;
                        acc[mt][nt][0] += bias[1024 + n0];
                        acc[mt][nt][1] += bias[1024 + n0 + 1];
                        acc[mt][nt][2] += bias[1024 + n0];
                        acc[mt][nt][3] += bias[1024 + n0 + 1];
                    }

                // per-(mt,rh) row max, quad-reduced
                float pm[2][2];
                #pragma unroll
                for (int mt = 0; mt < 2; ++mt)
                    #pragma unroll
                    for (int rh = 0; rh < 2; ++rh) {
                        float m = -3.4e38f;
                        #pragma unroll
                        for (int nt = 0; nt < 8; ++nt) {
                            m = fmaxf(m, acc[mt][nt][rh*2]);
                            m = fmaxf(m, acc[mt][nt][rh*2+1]);
                        }
                        m = fmaxf(m, __shfl_xor_sync(0xffffffffu, m, 1));
                        m = fmaxf(m, __shfl_xor_sync(0xffffffffu, m, 2));
                        pm[mt][rh] = m;
                        if (lq == 0) {
                            int r = wm * 32 + mt * 16 + rh * 8 + gID;
                            redm[r * 4 + wn] = m;
                        }
                    }
                __syncthreads();

                float M[2][2], S[2][2];
                #pragma unroll
                for (int mt = 0; mt < 2; ++mt)
                    #pragma unroll
                    for (int rh = 0; rh < 2; ++rh) {
                        int r = wm * 32 + mt * 16 + rh * 8 + gID;
                        float m = fmaxf(fmaxf(redm[r*4], redm[r*4+1]),
                                        fmaxf(redm[r*4+2], redm[r*4+3]));
                        M[mt][rh] = m;
                        float s = 0.0f;
                        #pragma unroll
                        for (int nt = 0; nt < 8; ++nt) {
                            s += __expf(acc[mt][nt][rh*2]   - m);
                            s += __expf(acc[mt][nt][rh*2+1] - m);
                        }
                        s += __shfl_xor_sync(0xffffffffu, s, 1);
                        s += __shfl_xor_sync(0xffffffffu, s, 2);
                        if (lq == 0) reds[r * 4 + wn] = s;
                        (void)pm;
                    }
                __syncthreads();

                #pragma unroll
                for (int mt = 0; mt < 2; ++mt)
                    #pragma unroll
                    for (int rh = 0; rh < 2; ++rh) {
                        int r = wm * 32 + mt * 16 + rh * 8 + gID;
                        float st = reds[r*4] + reds[r*4+1] + reds[r*4+2] + reds[r*4+3];
                        float lse = M[mt][rh] + logf(st);
                        S[mt][rh] = lse;
                    }

                #pragma unroll
                for (int mt = 0; mt < 2; ++mt)
                    #pragma unroll
                    for (int rh = 0; rh < 2; ++rh) {
                        int r = wm * 32 + mt * 16 + rh * 8 + gID;
                        float lse = S[mt][rh];
                        #pragma unroll
                        for (int nt = 0; nt < 8; ++nt) {
                            int n0 = wn * 64 + nt * 8 + lq * 2;
                            float2 o;
                            o.x = acc[mt][nt][rh*2]   - lse;
                            o.y = acc[mt][nt][rh*2+1] - lse;
                            *(float2*)(outLS + (size_t)(rbase + r) * 256 + n0) = o;
                        }
                    }
            }
        }
        __syncthreads();   // all warps done with this W buffer before reuse
    }
}

extern "C" void kernel_launch(void* const* d_in, const int* in_sizes, int n_in,
                              void* d_out, int out_size)
{
    (void)in_sizes; (void)n_in; (void)out_size;
    const float* input  = (const float*)d_in[0];
    const float* hidden = (const float*)d_in[1];
    const float* w_i2h  = (const float*)d_in[2];
    const float* b_i2h  = (const float*)d_in[3];
    const float* w_i2o  = (const float*)d_in[4];
    const float* b_i2o  = (const float*)d_in[5];
    float* out = (float*)d_out;

    repack_kernel<<<(NTILES * TILE_U32 + 255) / 256, 256>>>(w_i2h, w_i2o);

    cudaFuncSetAttribute(lstm_mma_kernel,
                         cudaFuncAttributeMaxDynamicSharedMemorySize,
                         SMEM_TOTAL);
    lstm_mma_kernel<<<BATCH / MT, THREADS, SMEM_TOTAL>>>(
        input, hidden, b_i2h, b_i2o, out);
}